// round 2
// baseline (speedup 1.0000x reference)
#include <cuda_runtime.h>
#include <cuda_bf16.h>
#include <cstdint>

// Problem constants: B=4, L=4096, D=1024, M_MAX=512
#define BB 4
#define LL 4096
#define DD 1024
#define MM 512

typedef unsigned long long u64;

// Scratch (static __device__ arrays are allowed; no runtime allocation)
__device__ float g_smoothed[BB * MM * DD];   // 8 MB
__device__ int   g_pbidx[BB * LL];           // 64 KB

// ---------------------------------------------------------------------------
// Kernel 1: gather boundary probs + EMA smoothing scan over M (sequential).
// grid = B, block = D (1024). Each thread owns one feature dim d.
// boundary_idx dtype (int32 vs int64) detected at runtime: for int32 data,
// words 1 and 3 are sorted indices >= 1; for int64 they are high halves == 0.
// ---------------------------------------------------------------------------
__global__ void ema_kernel(const float* __restrict__ ct,      // concept_tokens (B,M,D)
                           const float* __restrict__ bp,      // boundary_probs (B,L)
                           const int*   __restrict__ bidx)    // boundary_idx (B,M) i32 or i64
{
    const int b = blockIdx.x;
    const int d = threadIdx.x;
    __shared__ float p[MM];

    const bool is64 = (bidx[1] == 0 && bidx[3] == 0);

    if (d < MM) {
        int word = b * MM + d;
        if (is64) word <<= 1;            // little-endian low word of int64
        int ix = bidx[word];
        float pr = bp[b * LL + ix];      // concept_mask is all-True -> ignore
        p[d] = fmaxf(pr, 0.1f);
    }
    __syncthreads();

    const float* cb = ct + (size_t)b * MM * DD + d;
    float* sb = g_smoothed + (size_t)b * MM * DD + d;
    float h = cb[0];
    sb[0] = h;
#pragma unroll 8
    for (int m = 1; m < MM; m++) {
        float pm  = p[m];
        float dec = fmaxf(1.0f - pm, 1e-7f);
        h = dec * h + pm * cb[(size_t)m * DD];
        sb[(size_t)m * DD] = h;
    }
}

// ---------------------------------------------------------------------------
// Kernel 2: plug_back_idx = clip(cumsum(boundary_probs >= 0.5) - 1, 0)
// grid = B, block = 1024, 4 elements/thread, Hillis-Steele block scan.
// ---------------------------------------------------------------------------
__global__ void pbidx_kernel(const float* __restrict__ bp)
{
    const int b = blockIdx.x;
    const int t = threadIdx.x;
    __shared__ int s[1024];

    const float* row = bp + b * LL;
    int loc[4];
    int cnt = 0;
#pragma unroll
    for (int i = 0; i < 4; i++) {
        cnt += (row[t * 4 + i] >= 0.5f) ? 1 : 0;
        loc[i] = cnt;   // inclusive within this thread's chunk
    }
    s[t] = cnt;
    __syncthreads();

    for (int off = 1; off < 1024; off <<= 1) {
        int add = (t >= off) ? s[t - off] : 0;
        __syncthreads();
        s[t] += add;
        __syncthreads();
    }
    int excl = s[t] - cnt;
#pragma unroll
    for (int i = 0; i < 4; i++) {
        int tot = excl + loc[i];
        int v = tot - 1;
        g_pbidx[b * LL + t * 4 + i] = v < 0 ? 0 : v;
    }
}

// ---------------------------------------------------------------------------
// Kernel 3: out[row, e] = sum_d enc[row, d] * W[e, d] + smoothed[b, pbidx[row], e]
// M = B*L = 16384, N = D = 1024, K = D = 1024.
// 128x128x8 tile, 256 threads, 8x8 per thread (4+4 split fragments),
// packed fma.rn.f32x2 accumulation (2 FMA/instr -> ~2x fp32 throughput).
// ---------------------------------------------------------------------------
__global__ void __launch_bounds__(256, 2)
gemm_epilogue_kernel(const float* __restrict__ A,   // encoder_out, (16384, 1024)
                     const float* __restrict__ Wm,  // W, (1024, 1024) [e, d]
                     float* __restrict__ out)       // (16384, 1024)
{
    __shared__ float As[8][128];
    __shared__ float Bs[8][128];

    const int tid     = threadIdx.x;
    const int rowBase = blockIdx.y * 128;
    const int colBase = blockIdx.x * 128;

    const int lr = tid >> 1;          // 0..127
    const int lc = (tid & 1) << 2;    // 0 or 4 (k offset)

    const int ty = tid >> 4;          // 0..15
    const int tx = tid & 15;          // 0..15
    const int m0a = ty * 4;
    const int n0a = tx * 4;

    u64 acc2[8][4];
#pragma unroll
    for (int i = 0; i < 8; i++)
#pragma unroll
        for (int j = 0; j < 4; j++) acc2[i][j] = 0ull;

    const float* Aptr = A  + (size_t)(rowBase + lr) * DD + lc;
    const float* Wptr = Wm + (size_t)(colBase + lr) * DD + lc;

    for (int k0 = 0; k0 < DD; k0 += 8) {
        float4 av = *(const float4*)(Aptr + k0);
        float4 wv = *(const float4*)(Wptr + k0);
        As[lc + 0][lr] = av.x; As[lc + 1][lr] = av.y;
        As[lc + 2][lr] = av.z; As[lc + 3][lr] = av.w;
        Bs[lc + 0][lr] = wv.x; Bs[lc + 1][lr] = wv.y;
        Bs[lc + 2][lr] = wv.z; Bs[lc + 3][lr] = wv.w;
        __syncthreads();

#pragma unroll
        for (int k = 0; k < 8; k++) {
            float a[8];
            *(float4*)&a[0] = *(const float4*)&As[k][m0a];
            *(float4*)&a[4] = *(const float4*)&As[k][64 + m0a];
            float4 b0 = *(const float4*)&Bs[k][n0a];
            float4 b1 = *(const float4*)&Bs[k][64 + n0a];
            u64 bv[4];
            asm("mov.b64 %0, {%1, %2};" : "=l"(bv[0]) : "f"(b0.x), "f"(b0.y));
            asm("mov.b64 %0, {%1, %2};" : "=l"(bv[1]) : "f"(b0.z), "f"(b0.w));
            asm("mov.b64 %0, {%1, %2};" : "=l"(bv[2]) : "f"(b1.x), "f"(b1.y));
            asm("mov.b64 %0, {%1, %2};" : "=l"(bv[3]) : "f"(b1.z), "f"(b1.w));
#pragma unroll
            for (int i = 0; i < 8; i++) {
                u64 aa;
                asm("mov.b64 %0, {%1, %1};" : "=l"(aa) : "f"(a[i]));
#pragma unroll
                for (int j = 0; j < 4; j++)
                    asm("fma.rn.f32x2 %0, %1, %2, %0;"
                        : "+l"(acc2[i][j]) : "l"(aa), "l"(bv[j]));
            }
        }
        __syncthreads();
    }

    // Epilogue: add plugback gather, write out
#pragma unroll
    for (int i = 0; i < 8; i++) {
        const int row = rowBase + ((i < 4) ? (m0a + i) : (64 + m0a + i - 4));
        const int b   = row >> 12;                 // row / 4096
        const int idx = g_pbidx[row];
        const float* sp = g_smoothed + ((size_t)(b * MM + idx)) * DD;
        float* op = out + (size_t)row * DD;

        float x0, x1, x2, x3;
        asm("mov.b64 {%0, %1}, %2;" : "=f"(x0), "=f"(x1) : "l"(acc2[i][0]));
        asm("mov.b64 {%0, %1}, %2;" : "=f"(x2), "=f"(x3) : "l"(acc2[i][1]));
        {
            int c = colBase + n0a;
            float4 pv = *(const float4*)(sp + c);
            float4 ov = make_float4(x0 + pv.x, x1 + pv.y, x2 + pv.z, x3 + pv.w);
            *(float4*)(op + c) = ov;
        }
        asm("mov.b64 {%0, %1}, %2;" : "=f"(x0), "=f"(x1) : "l"(acc2[i][2]));
        asm("mov.b64 {%0, %1}, %2;" : "=f"(x2), "=f"(x3) : "l"(acc2[i][3]));
        {
            int c = colBase + 64 + n0a;
            float4 pv = *(const float4*)(sp + c);
            float4 ov = make_float4(x0 + pv.x, x1 + pv.y, x2 + pv.z, x3 + pv.w);
            *(float4*)(op + c) = ov;
        }
    }
}

// ---------------------------------------------------------------------------
// Launch: identify inputs by element count (robust to metadata ordering).
//   concept_tokens: 2,097,152   encoder_out: 16,777,216
//   boundary_probs: 16,384      W: 1,048,576
//   boundary_idx / concept_mask: both 2,048 (boundary_idx listed first)
// ---------------------------------------------------------------------------
extern "C" void kernel_launch(void* const* d_in, const int* in_sizes, int n_in,
                              void* d_out, int out_size)
{
    const float* ct   = nullptr;
    const float* enc  = nullptr;
    const float* bp   = nullptr;
    const int*   bidx = nullptr;
    const float* Wm   = nullptr;

    for (int i = 0; i < n_in; i++) {
        switch (in_sizes[i]) {
            case BB * MM * DD:  ct  = (const float*)d_in[i]; break;   // 2097152
            case BB * LL * DD:  enc = (const float*)d_in[i]; break;   // 16777216
            case BB * LL:       bp  = (const float*)d_in[i]; break;   // 16384
            case DD * DD:       Wm  = (const float*)d_in[i]; break;   // 1048576
            case BB * MM:       if (!bidx) bidx = (const int*)d_in[i]; break; // first 2048 = boundary_idx
            default: break;
        }
    }
    float* out = (float*)d_out;

    ema_kernel<<<BB, DD>>>(ct, bp, bidx);
    pbidx_kernel<<<BB, 1024>>>(bp);

    dim3 grid(DD / 128, (BB * LL) / 128);   // (8, 128)
    gemm_epilogue_kernel<<<grid, 256>>>(enc, Wm, out);
}

// round 4
// speedup vs baseline: 2.6031x; 2.6031x over previous
#include <cuda_runtime.h>
#include <cuda_bf16.h>
#include <cstdint>

#define BB 4
#define LL 4096
#define DD 1024
#define MM 512
#define CH 16
#define CHLEN 32

typedef unsigned long long u64;
typedef unsigned int u32;

// ---------------- scratch (static device arrays; no runtime alloc) ----------
__device__ float g_smoothed[BB * MM * DD];      // 8 MB
__device__ int   g_pbidx[BB * LL];              // 64 KB
__device__ float g_chainA[BB * CH];
__device__ float g_chainB[BB * CH * DD];        // 256 KB
__device__ __nv_bfloat16 g_ahi[BB * LL * DD];   // 32 MB
__device__ __nv_bfloat16 g_alo[BB * LL * DD];   // 32 MB
__device__ __nv_bfloat16 g_whi[DD * DD];        // 2 MB
__device__ __nv_bfloat16 g_wlo[DD * DD];        // 2 MB

__device__ __forceinline__ u32 smem_u32(const void* p) {
    u32 a;
    asm("{ .reg .u64 t; cvta.to.shared.u64 t, %1; cvt.u32.u64 %0, t; }" : "=r"(a) : "l"(p));
    return a;
}

// ---------------------------------------------------------------------------
// conv_split: fp32 -> (bf16 hi, bf16 lo) residual split
// ---------------------------------------------------------------------------
__global__ void conv_split(const float* __restrict__ x,
                           __nv_bfloat16* __restrict__ hi,
                           __nv_bfloat16* __restrict__ lo, int n4)
{
    int i = blockIdx.x * blockDim.x + threadIdx.x;
    if (i >= n4) return;
    float4 v = ((const float4*)x)[i];
    __nv_bfloat16 h0 = __float2bfloat16(v.x);
    __nv_bfloat16 h1 = __float2bfloat16(v.y);
    __nv_bfloat16 h2 = __float2bfloat16(v.z);
    __nv_bfloat16 h3 = __float2bfloat16(v.w);
    __nv_bfloat16 l0 = __float2bfloat16(v.x - __bfloat162float(h0));
    __nv_bfloat16 l1 = __float2bfloat16(v.y - __bfloat162float(h1));
    __nv_bfloat16 l2 = __float2bfloat16(v.z - __bfloat162float(h2));
    __nv_bfloat16 l3 = __float2bfloat16(v.w - __bfloat162float(h3));
    __nv_bfloat162* hp = (__nv_bfloat162*)hi;
    __nv_bfloat162* lp = (__nv_bfloat162*)lo;
    hp[i * 2 + 0] = __nv_bfloat162{h0, h1};
    hp[i * 2 + 1] = __nv_bfloat162{h2, h3};
    lp[i * 2 + 0] = __nv_bfloat162{l0, l1};
    lp[i * 2 + 1] = __nv_bfloat162{l2, l3};
}

// ---------------------------------------------------------------------------
// EMA phase 1: per-chunk local scan (h_in = 0), write h_local + chunk summary.
// ---------------------------------------------------------------------------
__global__ void ema1(const float* __restrict__ ct, const float* __restrict__ bp,
                     const int* __restrict__ bidx)
{
    const int c = blockIdx.x, b = blockIdx.y, d = threadIdx.x;
    __shared__ float p[CHLEN];
    const bool is64 = (bidx[1] == 0 && bidx[3] == 0);
    if (d < CHLEN) {
        int w = b * MM + c * CHLEN + d;
        if (is64) w <<= 1;
        p[d] = fmaxf(bp[b * LL + bidx[w]], 0.1f);
    }
    __syncthreads();

    const float* cb = ct + ((size_t)(b * MM + c * CHLEN)) * DD + d;
    float* sb = g_smoothed + ((size_t)(b * MM + c * CHLEN)) * DD + d;
    float h = 0.0f;
    int i0 = 0;
    if (c == 0) { h = cb[0]; sb[0] = h; i0 = 1; }
    for (int i = i0; i < CHLEN; i++) {
        float pm = p[i];
        float a = fmaxf(1.0f - pm, 1e-7f);
        h = a * h + pm * cb[(size_t)i * DD];
        sb[(size_t)i * DD] = h;
    }
    g_chainB[(b * CH + c) * DD + d] = h;
    if (d == 0) {
        float A = 1.0f;
        for (int i = i0; i < CHLEN; i++) A *= fmaxf(1.0f - p[i], 1e-7f);
        g_chainA[b * CH + c] = A;
    }
}

// ---------------------------------------------------------------------------
// EMA phase 2: fold chunk summaries -> h_in, add prefix*h_in to local scans.
// ---------------------------------------------------------------------------
__global__ void ema2(const float* __restrict__ bp, const int* __restrict__ bidx)
{
    const int c = blockIdx.x + 1, b = blockIdx.y, d = threadIdx.x;
    __shared__ float p[CHLEN];
    __shared__ float Aj[CH];
    const bool is64 = (bidx[1] == 0 && bidx[3] == 0);
    if (d < CHLEN) {
        int w = b * MM + c * CHLEN + d;
        if (is64) w <<= 1;
        p[d] = fmaxf(bp[b * LL + bidx[w]], 0.1f);
    }
    if (d >= 32 && d < 32 + CH) Aj[d - 32] = g_chainA[b * CH + (d - 32)];
    __syncthreads();

    float hin = 0.0f;
    for (int j = 0; j < c; j++)
        hin = Aj[j] * hin + g_chainB[(b * CH + j) * DD + d];

    float* sb = g_smoothed + ((size_t)(b * MM + c * CHLEN)) * DD + d;
    float pref = 1.0f;
    for (int i = 0; i < CHLEN; i++) {
        pref *= fmaxf(1.0f - p[i], 1e-7f);
        sb[(size_t)i * DD] += pref * hin;
    }
}

// ---------------------------------------------------------------------------
// plug_back_idx = clip(cumsum(bp >= 0.5) - 1, 0)
// ---------------------------------------------------------------------------
__global__ void pbidx_kernel(const float* __restrict__ bp)
{
    const int b = blockIdx.x, t = threadIdx.x;
    __shared__ int s[1024];
    const float* row = bp + b * LL;
    int loc[4];
    int cnt = 0;
#pragma unroll
    for (int i = 0; i < 4; i++) {
        cnt += (row[t * 4 + i] >= 0.5f) ? 1 : 0;
        loc[i] = cnt;
    }
    s[t] = cnt;
    __syncthreads();
    for (int off = 1; off < 1024; off <<= 1) {
        int add = (t >= off) ? s[t - off] : 0;
        __syncthreads();
        s[t] += add;
        __syncthreads();
    }
    int excl = s[t] - cnt;
#pragma unroll
    for (int i = 0; i < 4; i++) {
        int v = excl + loc[i] - 1;
        g_pbidx[b * LL + t * 4 + i] = v < 0 ? 0 : v;
    }
}

// ---------------------------------------------------------------------------
// HMMA bf16 split-GEMM + fused plugback epilogue.
// out[row,e] = sum_{3 phases} Ahat[row,:] . Bhat[e,:]  + smoothed[b, pbidx, e]
// phases: (a_hi,w_hi), (a_lo,w_hi), (a_hi,w_lo) -> 48 K64 chunks.
// Block 128x128, 8 warps (2m x 4n), warp tile 64x32, mma.m16n8k16.bf16.
// smem: 128B rows (64 bf16), XOR swizzle chunk^=(row&7); cp.async double-buffer.
// ---------------------------------------------------------------------------
#define NUM_T 48

__device__ __forceinline__ void load_chunk(int t, u32 sA, u32 sB,
                                           int rowBase, int colBase, int tid)
{
    const int phase = t >> 4;
    const int k0 = (t & 15) * 64;
    const __nv_bfloat16* Aarr = (phase == 1) ? g_alo : g_ahi;
    const __nv_bfloat16* Barr = (phase == 2) ? g_wlo : g_whi;
#pragma unroll
    for (int it = 0; it < 4; it++) {
        int c = tid + it * 256;
        int row = c >> 3, ch = c & 7;
        u32 dst = sA + row * 128 + (u32)((ch ^ (row & 7)) << 4);
        const void* src = Aarr + ((size_t)(rowBase + row) << 10) + k0 + ch * 8;
        asm volatile("cp.async.cg.shared.global [%0], [%1], 16;" :: "r"(dst), "l"(src));
    }
#pragma unroll
    for (int it = 0; it < 4; it++) {
        int c = tid + it * 256;
        int row = c >> 3, ch = c & 7;
        u32 dst = sB + row * 128 + (u32)((ch ^ (row & 7)) << 4);
        const void* src = Barr + ((size_t)(colBase + row) << 10) + k0 + ch * 8;
        asm volatile("cp.async.cg.shared.global [%0], [%1], 16;" :: "r"(dst), "l"(src));
    }
    asm volatile("cp.async.commit_group;");
}

__global__ void __launch_bounds__(256, 2) gemm_hmma(float* __restrict__ out)
{
    extern __shared__ char smem[];
    const u32 sbase = smem_u32(smem);
    const int tid = threadIdx.x;
    const int wid = tid >> 5, lane = tid & 31;
    const int rowBase = blockIdx.y * 128;
    const int colBase = blockIdx.x * 128;
    const int wm = (wid >> 2) * 64;       // warp m offset (0 or 64)
    const int wn = (wid & 3) * 32;        // warp n offset (0,32,64,96)

    const u32 sAb[2] = { sbase,         sbase + 32768 };
    const u32 sBb[2] = { sbase + 16384, sbase + 49152 };

    float acc[4][4][4];                   // [mi][n8][reg]
#pragma unroll
    for (int i = 0; i < 4; i++)
#pragma unroll
        for (int j = 0; j < 4; j++)
#pragma unroll
            for (int k = 0; k < 4; k++) acc[i][j][k] = 0.0f;

    load_chunk(0, sAb[0], sBb[0], rowBase, colBase, tid);

    for (int t = 0; t < NUM_T; t++) {
        if (t + 1 < NUM_T) {
            load_chunk(t + 1, sAb[(t + 1) & 1], sBb[(t + 1) & 1], rowBase, colBase, tid);
            asm volatile("cp.async.wait_group 1;");
        } else {
            asm volatile("cp.async.wait_group 0;");
        }
        __syncthreads();

        const u32 sa = sAb[t & 1], sb = sBb[t & 1];
#pragma unroll
        for (int ks = 0; ks < 4; ks++) {
            u32 a[4][4];
#pragma unroll
            for (int mi = 0; mi < 4; mi++) {
                int row = wm + mi * 16 + (lane & 15);
                int ch  = ks * 2 + (lane >> 4);
                u32 ad = sa + row * 128 + (u32)((ch ^ (row & 7)) << 4);
                asm volatile("ldmatrix.sync.aligned.m8n8.x4.shared.b16 {%0,%1,%2,%3}, [%4];"
                             : "=r"(a[mi][0]), "=r"(a[mi][1]), "=r"(a[mi][2]), "=r"(a[mi][3])
                             : "r"(ad));
            }
            u32 bf[2][4];
#pragma unroll
            for (int nj = 0; nj < 2; nj++) {
                int row = wn + nj * 16 + (lane & 7) + ((lane >> 4) << 3);
                int ch  = ks * 2 + ((lane >> 3) & 1);
                u32 ad = sb + row * 128 + (u32)((ch ^ (row & 7)) << 4);
                asm volatile("ldmatrix.sync.aligned.m8n8.x4.shared.b16 {%0,%1,%2,%3}, [%4];"
                             : "=r"(bf[nj][0]), "=r"(bf[nj][1]), "=r"(bf[nj][2]), "=r"(bf[nj][3])
                             : "r"(ad));
            }
#pragma unroll
            for (int mi = 0; mi < 4; mi++)
#pragma unroll
                for (int n8 = 0; n8 < 4; n8++) {
                    u32 b0 = bf[n8 >> 1][(n8 & 1) * 2 + 0];
                    u32 b1 = bf[n8 >> 1][(n8 & 1) * 2 + 1];
                    asm volatile(
                        "mma.sync.aligned.m16n8k16.row.col.f32.bf16.bf16.f32 "
                        "{%0,%1,%2,%3}, {%4,%5,%6,%7}, {%8,%9}, {%0,%1,%2,%3};"
                        : "+f"(acc[mi][n8][0]), "+f"(acc[mi][n8][1]),
                          "+f"(acc[mi][n8][2]), "+f"(acc[mi][n8][3])
                        : "r"(a[mi][0]), "r"(a[mi][1]), "r"(a[mi][2]), "r"(a[mi][3]),
                          "r"(b0), "r"(b1));
                }
        }
        __syncthreads();
    }

    // Epilogue: d0,d1 -> row g cols 2t,2t+1 ; d2,d3 -> row g+8
    const int g = lane >> 2, tq = lane & 3;
#pragma unroll
    for (int mi = 0; mi < 4; mi++) {
#pragma unroll
        for (int half = 0; half < 2; half++) {
            const int row = rowBase + wm + mi * 16 + g + half * 8;
            const int b = row >> 12;
            const int idx = g_pbidx[row];
            const float* sp = g_smoothed + ((size_t)(b * MM + idx)) * DD;
            float* op = out + (size_t)row * DD;
#pragma unroll
            for (int n8 = 0; n8 < 4; n8++) {
                const int col = colBase + wn + n8 * 8 + tq * 2;
                float2 pv = *(const float2*)(sp + col);
                float2 ov;
                ov.x = acc[mi][n8][half * 2 + 0] + pv.x;
                ov.y = acc[mi][n8][half * 2 + 1] + pv.y;
                *(float2*)(op + col) = ov;
            }
        }
    }
}

// ---------------------------------------------------------------------------
// Launch
// ---------------------------------------------------------------------------
extern "C" void kernel_launch(void* const* d_in, const int* in_sizes, int n_in,
                              void* d_out, int out_size)
{
    const float* ct = nullptr;
    const float* enc = nullptr;
    const float* bp = nullptr;
    const int* bidx = nullptr;
    const float* Wm = nullptr;

    for (int i = 0; i < n_in; i++) {
        switch (in_sizes[i]) {
            case BB * MM * DD: ct  = (const float*)d_in[i]; break;
            case BB * LL * DD: enc = (const float*)d_in[i]; break;
            case BB * LL:      bp  = (const float*)d_in[i]; break;
            case DD * DD:      Wm  = (const float*)d_in[i]; break;
            case BB * MM:      if (!bidx) bidx = (const int*)d_in[i]; break;
            default: break;
        }
    }
    float* out = (float*)d_out;

    static __nv_bfloat16* ahi_p = nullptr;
    static __nv_bfloat16* alo_p = nullptr;
    static __nv_bfloat16* whi_p = nullptr;
    static __nv_bfloat16* wlo_p = nullptr;
    if (!ahi_p) {
        cudaGetSymbolAddress((void**)&ahi_p, g_ahi);
        cudaGetSymbolAddress((void**)&alo_p, g_alo);
        cudaGetSymbolAddress((void**)&whi_p, g_whi);
        cudaGetSymbolAddress((void**)&wlo_p, g_wlo);
        cudaFuncSetAttribute(gemm_hmma, cudaFuncAttributeMaxDynamicSharedMemorySize, 65536);
    }

    conv_split<<<(BB * LL * DD / 4 + 255) / 256, 256>>>(enc, ahi_p, alo_p, BB * LL * DD / 4);
    conv_split<<<(DD * DD / 4 + 255) / 256, 256>>>(Wm, whi_p, wlo_p, DD * DD / 4);
    ema1<<<dim3(CH, BB), 1024>>>(ct, bp, bidx);
    ema2<<<dim3(CH - 1, BB), 1024>>>(bp, bidx);
    pbidx_kernel<<<BB, 1024>>>(bp);

    dim3 grid(DD / 128, (BB * LL) / 128);   // (8, 128)
    gemm_hmma<<<grid, 256, 65536>>>(out);
}

// round 5
// speedup vs baseline: 3.0053x; 1.1545x over previous
#include <cuda_runtime.h>
#include <cuda_bf16.h>
#include <cstdint>

#define BB 4
#define LL 4096
#define DD 1024
#define MM 512
#define CH 16
#define CHLEN 32

typedef unsigned long long u64;
typedef unsigned int u32;

// ---------------- scratch (static device arrays; no runtime alloc) ----------
__device__ float g_smoothed[BB * MM * DD];      // 8 MB
__device__ int   g_pbidx[BB * LL];              // 64 KB
__device__ float g_chainA[BB * CH];
__device__ float g_chainB[BB * CH * DD];        // 256 KB

// ---------------------------------------------------------------------------
// EMA phase 1: per-chunk local scan (h_in = 0), write h_local + chunk summary.
// ---------------------------------------------------------------------------
__global__ void ema1(const float* __restrict__ ct, const float* __restrict__ bp,
                     const int* __restrict__ bidx)
{
    const int c = blockIdx.x, b = blockIdx.y, d = threadIdx.x;
    __shared__ float p[CHLEN];
    const bool is64 = (bidx[1] == 0 && bidx[3] == 0);
    if (d < CHLEN) {
        int w = b * MM + c * CHLEN + d;
        if (is64) w <<= 1;
        p[d] = fmaxf(bp[b * LL + bidx[w]], 0.1f);
    }
    __syncthreads();

    const float* cb = ct + ((size_t)(b * MM + c * CHLEN)) * DD + d;
    float* sb = g_smoothed + ((size_t)(b * MM + c * CHLEN)) * DD + d;
    float h = 0.0f;
    int i0 = 0;
    if (c == 0) { h = cb[0]; sb[0] = h; i0 = 1; }
    for (int i = i0; i < CHLEN; i++) {
        float pm = p[i];
        float a = fmaxf(1.0f - pm, 1e-7f);
        h = a * h + pm * cb[(size_t)i * DD];
        sb[(size_t)i * DD] = h;
    }
    g_chainB[(b * CH + c) * DD + d] = h;
    if (d == 0) {
        float A = 1.0f;
        for (int i = i0; i < CHLEN; i++) A *= fmaxf(1.0f - p[i], 1e-7f);
        g_chainA[b * CH + c] = A;
    }
}

// ---------------------------------------------------------------------------
// EMA phase 2: fold chunk summaries -> h_in, add prefix*h_in to local scans.
// ---------------------------------------------------------------------------
__global__ void ema2(const float* __restrict__ bp, const int* __restrict__ bidx)
{
    const int c = blockIdx.x + 1, b = blockIdx.y, d = threadIdx.x;
    __shared__ float p[CHLEN];
    __shared__ float Aj[CH];
    const bool is64 = (bidx[1] == 0 && bidx[3] == 0);
    if (d < CHLEN) {
        int w = b * MM + c * CHLEN + d;
        if (is64) w <<= 1;
        p[d] = fmaxf(bp[b * LL + bidx[w]], 0.1f);
    }
    if (d >= 32 && d < 32 + CH) Aj[d - 32] = g_chainA[b * CH + (d - 32)];
    __syncthreads();

    float hin = 0.0f;
    for (int j = 0; j < c; j++)
        hin = Aj[j] * hin + g_chainB[(b * CH + j) * DD + d];

    float* sb = g_smoothed + ((size_t)(b * MM + c * CHLEN)) * DD + d;
    float pref = 1.0f;
    for (int i = 0; i < CHLEN; i++) {
        pref *= fmaxf(1.0f - p[i], 1e-7f);
        sb[(size_t)i * DD] += pref * hin;
    }
}

// ---------------------------------------------------------------------------
// plug_back_idx = clip(cumsum(bp >= 0.5) - 1, 0)
// ---------------------------------------------------------------------------
__global__ void pbidx_kernel(const float* __restrict__ bp)
{
    const int b = blockIdx.x, t = threadIdx.x;
    __shared__ int s[1024];
    const float* row = bp + b * LL;
    int loc[4];
    int cnt = 0;
#pragma unroll
    for (int i = 0; i < 4; i++) {
        cnt += (row[t * 4 + i] >= 0.5f) ? 1 : 0;
        loc[i] = cnt;
    }
    s[t] = cnt;
    __syncthreads();
    for (int off = 1; off < 1024; off <<= 1) {
        int add = (t >= off) ? s[t - off] : 0;
        __syncthreads();
        s[t] += add;
        __syncthreads();
    }
    int excl = s[t] - cnt;
#pragma unroll
    for (int i = 0; i < 4; i++) {
        int v = excl + loc[i] - 1;
        g_pbidx[b * LL + t * 4 + i] = v < 0 ? 0 : v;
    }
}

// ---------------------------------------------------------------------------
// TF32 single-pass GEMM + fused plugback epilogue.
// out[row,e] = enc[row,:] . W[e,:] + smoothed[b, pbidx[row], e]
// Block 128x128, 8 warps (2m x 4n), warp tile 64x32, mma.m16n8k8.tf32.
// fp32 tiles in smem, row stride 36 words (36 mod 32 == 4 => the fragment
// access pattern bank = (row*4 + k) & 31 is conflict-free for all lanes).
// K-chunk 32, cp.async double-buffered.
// ---------------------------------------------------------------------------
#define KC 32
#define NCHUNK 32
#define ROWSTRIDE_B 144   // 36 words
#define TILE_BYTES (128 * ROWSTRIDE_B)   // 18432

__device__ __forceinline__ u32 smem_u32(const void* p) {
    u32 a;
    asm("{ .reg .u64 t; cvta.to.shared.u64 t, %1; cvt.u32.u64 %0, t; }" : "=r"(a) : "l"(p));
    return a;
}
__device__ __forceinline__ u32 f2tf32(float v) {
    u32 r;
    asm("cvt.rna.tf32.f32 %0, %1;" : "=r"(r) : "f"(v));
    return r;
}

__device__ __forceinline__ void load_chunk(int t, u32 sA, u32 sB,
                                           const float* __restrict__ A,
                                           const float* __restrict__ Wm,
                                           int rowBase, int colBase, int tid)
{
    const int k0 = t * KC;
#pragma unroll
    for (int it = 0; it < 4; it++) {
        int c = tid + it * 256;
        int row = c >> 3, cc = c & 7;       // 8 x 16B per 128B row
        u32 dst = sA + row * ROWSTRIDE_B + cc * 16;
        const void* src = A + ((size_t)(rowBase + row) << 10) + k0 + cc * 4;
        asm volatile("cp.async.cg.shared.global [%0], [%1], 16;" :: "r"(dst), "l"(src));
    }
#pragma unroll
    for (int it = 0; it < 4; it++) {
        int c = tid + it * 256;
        int row = c >> 3, cc = c & 7;
        u32 dst = sB + row * ROWSTRIDE_B + cc * 16;
        const void* src = Wm + ((size_t)(colBase + row) << 10) + k0 + cc * 4;
        asm volatile("cp.async.cg.shared.global [%0], [%1], 16;" :: "r"(dst), "l"(src));
    }
    asm volatile("cp.async.commit_group;");
}

__global__ void __launch_bounds__(256, 2)
gemm_tf32(const float* __restrict__ A, const float* __restrict__ Wm,
          float* __restrict__ out)
{
    extern __shared__ char smem[];
    const u32 sbase = smem_u32(smem);
    const int tid = threadIdx.x;
    const int wid = tid >> 5, lane = tid & 31;
    const int rowBase = blockIdx.y * 128;
    const int colBase = blockIdx.x * 128;
    const int wm = (wid >> 2) * 64;
    const int wn = (wid & 3) * 32;
    const int g = lane >> 2, tq = lane & 3;

    const u32 sAb[2] = { sbase,                  sbase + 2 * TILE_BYTES };
    const u32 sBb[2] = { sbase + TILE_BYTES,     sbase + 3 * TILE_BYTES };

    float acc[4][4][4];
#pragma unroll
    for (int i = 0; i < 4; i++)
#pragma unroll
        for (int j = 0; j < 4; j++)
#pragma unroll
            for (int k = 0; k < 4; k++) acc[i][j][k] = 0.0f;

    load_chunk(0, sAb[0], sBb[0], A, Wm, rowBase, colBase, tid);

    for (int t = 0; t < NCHUNK; t++) {
        if (t + 1 < NCHUNK) {
            load_chunk(t + 1, sAb[(t + 1) & 1], sBb[(t + 1) & 1], A, Wm,
                       rowBase, colBase, tid);
            asm volatile("cp.async.wait_group 1;");
        } else {
            asm volatile("cp.async.wait_group 0;");
        }
        __syncthreads();

        const char* sa = smem + (size_t)((t & 1) ? 2 * TILE_BYTES : 0);
        const char* sb = smem + (size_t)((t & 1) ? 3 * TILE_BYTES : TILE_BYTES);

#pragma unroll
        for (int ks = 0; ks < 4; ks++) {
            const int kk = ks * 8 + tq;
            u32 a[4][4];
#pragma unroll
            for (int mi = 0; mi < 4; mi++) {
                const int r0 = wm + mi * 16 + g;
                const char* pr0 = sa + r0 * ROWSTRIDE_B;
                const char* pr1 = sa + (r0 + 8) * ROWSTRIDE_B;
                a[mi][0] = f2tf32(*(const float*)(pr0 + kk * 4));
                a[mi][1] = f2tf32(*(const float*)(pr1 + kk * 4));
                a[mi][2] = f2tf32(*(const float*)(pr0 + (kk + 4) * 4));
                a[mi][3] = f2tf32(*(const float*)(pr1 + (kk + 4) * 4));
            }
            u32 bfr[4][2];
#pragma unroll
            for (int n8 = 0; n8 < 4; n8++) {
                const int c0 = wn + n8 * 8 + g;
                const char* pc = sb + c0 * ROWSTRIDE_B;
                bfr[n8][0] = f2tf32(*(const float*)(pc + kk * 4));
                bfr[n8][1] = f2tf32(*(const float*)(pc + (kk + 4) * 4));
            }
#pragma unroll
            for (int mi = 0; mi < 4; mi++)
#pragma unroll
                for (int n8 = 0; n8 < 4; n8++) {
                    asm volatile(
                        "mma.sync.aligned.m16n8k8.row.col.f32.tf32.tf32.f32 "
                        "{%0,%1,%2,%3}, {%4,%5,%6,%7}, {%8,%9}, {%0,%1,%2,%3};"
                        : "+f"(acc[mi][n8][0]), "+f"(acc[mi][n8][1]),
                          "+f"(acc[mi][n8][2]), "+f"(acc[mi][n8][3])
                        : "r"(a[mi][0]), "r"(a[mi][1]), "r"(a[mi][2]), "r"(a[mi][3]),
                          "r"(bfr[n8][0]), "r"(bfr[n8][1]));
                }
        }
        __syncthreads();
    }

    // Epilogue: acc d0,d1 -> row g, cols 2tq,2tq+1 ; d2,d3 -> row g+8
#pragma unroll
    for (int mi = 0; mi < 4; mi++) {
#pragma unroll
        for (int half = 0; half < 2; half++) {
            const int row = rowBase + wm + mi * 16 + g + half * 8;
            const int b = row >> 12;
            const int idx = g_pbidx[row];
            const float* sp = g_smoothed + ((size_t)(b * MM + idx)) * DD;
            float* op = out + (size_t)row * DD;
#pragma unroll
            for (int n8 = 0; n8 < 4; n8++) {
                const int col = colBase + wn + n8 * 8 + tq * 2;
                float2 pv = *(const float2*)(sp + col);
                float2 ov;
                ov.x = acc[mi][n8][half * 2 + 0] + pv.x;
                ov.y = acc[mi][n8][half * 2 + 1] + pv.y;
                *(float2*)(op + col) = ov;
            }
        }
    }
}

// ---------------------------------------------------------------------------
// Launch
// ---------------------------------------------------------------------------
extern "C" void kernel_launch(void* const* d_in, const int* in_sizes, int n_in,
                              void* d_out, int out_size)
{
    const float* ct = nullptr;
    const float* enc = nullptr;
    const float* bp = nullptr;
    const int* bidx = nullptr;
    const float* Wm = nullptr;

    for (int i = 0; i < n_in; i++) {
        switch (in_sizes[i]) {
            case BB * MM * DD: ct  = (const float*)d_in[i]; break;
            case BB * LL * DD: enc = (const float*)d_in[i]; break;
            case BB * LL:      bp  = (const float*)d_in[i]; break;
            case DD * DD:      Wm  = (const float*)d_in[i]; break;
            case BB * MM:      if (!bidx) bidx = (const int*)d_in[i]; break;
            default: break;
        }
    }
    float* out = (float*)d_out;

    static bool inited = false;
    if (!inited) {
        cudaFuncSetAttribute(gemm_tf32, cudaFuncAttributeMaxDynamicSharedMemorySize,
                             4 * TILE_BYTES);
        inited = true;
    }

    ema1<<<dim3(CH, BB), 1024>>>(ct, bp, bidx);
    ema2<<<dim3(CH - 1, BB), 1024>>>(bp, bidx);
    pbidx_kernel<<<BB, 1024>>>(bp);

    dim3 grid(DD / 128, (BB * LL) / 128);   // (8, 128)
    gemm_tf32<<<grid, 256, 4 * TILE_BYTES>>>(enc, Wm, out);
}